// round 8
// baseline (speedup 1.0000x reference)
#include <cuda_runtime.h>
#include <cuda_bf16.h>
#include <math.h>
#include <cstdint>

#define NPTS  768
#define NHALF 384
#define DDIM  64
#define NPER  200
#define NKER  4
#define NSLOT 201     // 200 perms + identity(200)
#define PSLOTS 256    // padded p dimension (4 tiles of 64)

#define INV_NN (1.0f/147072.0f)    // 384*383
#define INV_NM (1.0f/147456.0f)    // 384*384
#define C1 (2.0f*INV_NN + 2.0f*INV_NM)
#define C14 (0.25f*C1)
#define C4 (2.0f*INV_NM)
// cst' small constant, computed analytically in double to avoid cancellation:
// 0.5*(1/nn - 1/nm)
#define CS ((float)(0.5*(1.0/147072.0 - 1.0/147456.0)))

// ---------------- scratch (device globals; zero-initialized) -------------
__device__ __nv_bfloat16 g_Khi[NKER][NPTS * NPTS];   // 4.5 MB
__device__ __nv_bfloat16 g_Kmd[NKER][NPTS * NPTS];   // 4.5 MB
__device__ __nv_bfloat16 g_Klo[NKER][NPTS * NPTS];   // 4.5 MB
__device__ __nv_bfloat16 g_mbf[PSLOTS][NPTS];        // signed mask rows (+1/-1)
__device__ float g_rowP[NKER][12][NPTS];             // row partials per col-tile
__device__ float g_diag[NKER][NPTS];
__device__ float g_z[NKER][NHALF];                   // K[384+i][i] (pre-zero value)
__device__ float g_W[NKER][NPTS];                    // (col-row)/nm = +-z/nm
__device__ float g_cst[NKER];                        // S*CS - Dt/nn
__device__ float g_part[NKER][12][PSLOTS];           // T partials per b-subtile

// ---------------- helpers ----------------
__device__ __forceinline__ float warpred(float v) {
    #pragma unroll
    for (int o = 16; o > 0; o >>= 1) v += __shfl_down_sync(0xffffffffu, v, o);
    return v;
}

__device__ __forceinline__ uint32_t s2u(const void* p) {
    uint32_t r;
    asm("{ .reg .u64 t; cvta.to.shared.u64 t, %1; cvt.u32.u64 %0, t; }"
        : "=r"(r) : "l"(p));
    return r;
}

// ---------------- kernel 1: pairwise kernel matrices (bf16 3-way) --------
__global__ void __launch_bounds__(256) k_pairK(const float* __restrict__ X,
                                               const float* __restrict__ Y,
                                               const float* __restrict__ bw) {
    __shared__ float Zi[64][65];
    __shared__ float Zj[64][65];
    __shared__ float sqi[64], sqj[64];
    const int i0 = blockIdx.y * 64, j0 = blockIdx.x * 64;
    const int tid = threadIdx.x;

    for (int idx = tid; idx < 64 * 64; idx += 256) {
        int r = idx >> 6, d = idx & 63;
        int gi = i0 + r;
        Zi[r][d] = (gi < NHALF) ? X[gi * DDIM + d] : Y[(gi - NHALF) * DDIM + d];
        int gj = j0 + r;
        Zj[r][d] = (gj < NHALF) ? X[gj * DDIM + d] : Y[(gj - NHALF) * DDIM + d];
    }
    __syncthreads();

    if (tid < 64) {
        float s = 0.f;
        #pragma unroll
        for (int d = 0; d < 64; d++) { float v = Zi[tid][d]; s += v * v; }
        sqi[tid] = s;
    } else if (tid < 128) {
        int r = tid - 64;
        float s = 0.f;
        #pragma unroll
        for (int d = 0; d < 64; d++) { float v = Zj[r][d]; s += v * v; }
        sqj[r] = s;
    }
    __syncthreads();

    const int tx = tid & 15, ty = tid >> 4;
    float acc[4][4] = {};
    #pragma unroll 4
    for (int d = 0; d < 64; d++) {
        float a0 = Zi[ty * 4 + 0][d], a1 = Zi[ty * 4 + 1][d];
        float a2 = Zi[ty * 4 + 2][d], a3 = Zi[ty * 4 + 3][d];
        float b0 = Zj[tx * 4 + 0][d], b1 = Zj[tx * 4 + 1][d];
        float b2 = Zj[tx * 4 + 2][d], b3 = Zj[tx * 4 + 3][d];
        acc[0][0] += a0 * b0; acc[0][1] += a0 * b1; acc[0][2] += a0 * b2; acc[0][3] += a0 * b3;
        acc[1][0] += a1 * b0; acc[1][1] += a1 * b1; acc[1][2] += a1 * b2; acc[1][3] += a1 * b3;
        acc[2][0] += a2 * b0; acc[2][1] += a2 * b1; acc[2][2] += a2 * b2; acc[2][3] += a2 * b3;
        acc[3][0] += a3 * b0; acc[3][1] += a3 * b1; acc[3][2] += a3 * b2; acc[3][3] += a3 * b3;
    }

    const float ig0 = 1.f / (bw[0] * bw[0]);
    const float il1 = 1.f / bw[1];
    const float ig2 = 1.f / (bw[2] * bw[2]);
    const float il3 = 1.f / bw[3];

    float rp[NKER][4] = {};   // row partials over this block's 64 cols

    #pragma unroll
    for (int ii = 0; ii < 4; ii++) {
        const int gi = i0 + ty * 4 + ii;
        const float si = sqi[ty * 4 + ii];
        union { __nv_bfloat16 b[4]; uint2 u; } hb[NKER], mb[NKER], lb[NKER];
        #pragma unroll
        for (int jj = 0; jj < 4; jj++) {
            const int gj = j0 + tx * 4 + jj;
            float d2 = si + sqj[tx * 4 + jj] - 2.f * acc[ii][jj];
            d2 = fmaxf(d2, 0.f);
            float dist = sqrtf(d2 + 1e-12f);
            float dd = dist * dist;
            float kv[NKER];
            kv[0] = __expf(-dd * ig0);
            kv[1] = __expf(-dist * il1);
            kv[2] = __expf(-dd * ig2);
            kv[3] = __expf(-dist * il3);
            if (gi == gj + NHALF) {
                g_z[0][gj] = kv[0]; g_z[1][gj] = kv[1];
                g_z[2][gj] = kv[2]; g_z[3][gj] = kv[3];
            }
            if (gi == gj) {
                g_diag[0][gi] = kv[0]; g_diag[1][gi] = kv[1];
                g_diag[2][gi] = kv[2]; g_diag[3][gi] = kv[3];
            }
            if (gi < NHALF && gj == gi + NHALF) {
                kv[0] = kv[1] = kv[2] = kv[3] = 0.f;
            }
            #pragma unroll
            for (int k = 0; k < NKER; k++) {
                rp[k][ii] += kv[k];
                __nv_bfloat16 h = __float2bfloat16(kv[k]);
                float r1 = kv[k] - __bfloat162float(h);
                __nv_bfloat16 m = __float2bfloat16(r1);
                float r2 = r1 - __bfloat162float(m);
                hb[k].b[jj] = h;
                mb[k].b[jj] = m;
                lb[k].b[jj] = __float2bfloat16(r2);
            }
        }
        const size_t base = (size_t)gi * NPTS + j0 + tx * 4;
        #pragma unroll
        for (int k = 0; k < NKER; k++) {
            *(uint2*)&g_Khi[k][base] = hb[k].u;
            *(uint2*)&g_Kmd[k][base] = mb[k].u;
            *(uint2*)&g_Klo[k][base] = lb[k].u;
        }
    }

    #pragma unroll
    for (int k = 0; k < NKER; k++) {
        #pragma unroll
        for (int ii = 0; ii < 4; ii++) {
            float v = rp[k][ii];
            v += __shfl_xor_sync(0xffffffffu, v, 1);
            v += __shfl_xor_sync(0xffffffffu, v, 2);
            v += __shfl_xor_sync(0xffffffffu, v, 4);
            v += __shfl_xor_sync(0xffffffffu, v, 8);
            if (tx == 0) g_rowP[k][blockIdx.x][i0 + ty * 4 + ii] = v;
        }
    }
}

// ---------------- kernel 2: signed mask rows: +1 on A, -1 on B ----------
__global__ void k_maskset(const int* __restrict__ perms) {
    const int p = blockIdx.x;          // 201
    const int j = threadIdx.x;         // 768
    const __nv_bfloat16 v = __float2bfloat16(j < NHALF ? 1.f : -1.f);
    if (p < NPER) g_mbf[p][perms[p * NPTS + j]] = v;
    else          g_mbf[p][j] = v;     // identity slot
}

// ---------------- kernel 3: mma.sync signed GEMM -> T partials -----------
// D'[p][b] = sum_a s[p][a] * Kstored[b][a]; T = sum_b s[p][b] * D'[p][b].
// grid (6 n-tiles, 4 p-tiles, 4 kernels), 256 threads (8 warps: 4 m x 2 n).
// k-dim = 2304 (hi, mid, lo; mask repeated).
__global__ void __launch_bounds__(256) k_mma() {
    __shared__ __align__(16) unsigned char As[2][64 * 128];    // 16 KB
    __shared__ __align__(16) unsigned char Bs[2][128 * 128];   // 32 KB
    const int nt = blockIdx.x, pt = blockIdx.y, kk = blockIdx.z;
    const int tid = threadIdx.x, w = tid >> 5, lane = tid & 31;
    const int wm = w & 3, wn = w >> 2;
    const uint32_t aBase = s2u(&As[0][0]);
    const uint32_t bBase = s2u(&Bs[0][0]);

    float d[8][4] = {};

    auto load = [&](int ch, int buf) {
        const int a0 = (ch % 12) * 64;
        const __nv_bfloat16* __restrict__ KP =
            (ch < 12) ? g_Khi[kk] : (ch < 24) ? g_Kmd[kk] : g_Klo[kk];
        #pragma unroll 2
        for (int idx = tid; idx < 512; idx += 256) {        // A: 64 rows x 128B
            int r = idx >> 3, c = idx & 7;
            uint4 v = *(const uint4*)&g_mbf[pt * 64 + r][a0 + c * 8];
            *(uint4*)&As[buf][r * 128 + ((c ^ (r & 7)) << 4)] = v;
        }
        #pragma unroll 4
        for (int idx = tid; idx < 1024; idx += 256) {       // B: 128 rows x 128B
            int r = idx >> 3, c = idx & 7;
            uint4 v = *(const uint4*)&KP[(size_t)(nt * 128 + r) * NPTS + a0 + c * 8];
            *(uint4*)&Bs[buf][r * 128 + ((c ^ (r & 7)) << 4)] = v;
        }
    };

    load(0, 0);
    __syncthreads();
    for (int ch = 0; ch < 36; ch++) {
        const int buf = ch & 1;
        if (ch + 1 < 36) load(ch + 1, buf ^ 1);
        #pragma unroll
        for (int ks = 0; ks < 4; ks++) {
            uint32_t a[4];
            {
                int r = wm * 16 + (lane & 15);
                int c = ks * 2 + (lane >> 4);
                uint32_t addr = aBase + buf * 8192 + r * 128 + ((c ^ (r & 7)) << 4);
                asm volatile("ldmatrix.sync.aligned.m8n8.x4.shared.b16 {%0,%1,%2,%3}, [%4];"
                             : "=r"(a[0]), "=r"(a[1]), "=r"(a[2]), "=r"(a[3]) : "r"(addr));
            }
            #pragma unroll
            for (int j = 0; j < 8; j++) {
                uint32_t b[2];
                int r = wn * 64 + j * 8 + (lane & 7);
                int c = ks * 2 + ((lane >> 3) & 1);
                uint32_t addr = bBase + buf * 16384 + r * 128 + ((c ^ (r & 7)) << 4);
                asm volatile("ldmatrix.sync.aligned.m8n8.x2.shared.b16 {%0,%1}, [%2];"
                             : "=r"(b[0]), "=r"(b[1]) : "r"(addr));
                asm volatile("mma.sync.aligned.m16n8k16.row.col.f32.bf16.bf16.f32 "
                             "{%0,%1,%2,%3}, {%4,%5,%6,%7}, {%8,%9}, {%0,%1,%2,%3};"
                             : "+f"(d[j][0]), "+f"(d[j][1]), "+f"(d[j][2]), "+f"(d[j][3])
                             : "r"(a[0]), "r"(a[1]), "r"(a[2]), "r"(a[3]),
                               "r"(b[0]), "r"(b[1]));
            }
        }
        __syncthreads();
    }

    // epilogue: partial T[p] = sum_b s[p][b] * D'[p][b]
    const int lq = lane >> 2, lr = lane & 3;
    const int p0 = pt * 64 + wm * 16 + lq;
    const int p1 = p0 + 8;
    float part0 = 0.f, part1 = 0.f;
    #pragma unroll
    for (int j = 0; j < 8; j++) {
        int b0 = nt * 128 + wn * 64 + j * 8 + lr * 2;
        float m0 = __bfloat162float(g_mbf[p0][b0]);
        float m1 = __bfloat162float(g_mbf[p0][b0 + 1]);
        part0 += d[j][0] * m0 + d[j][1] * m1;
        float n0 = __bfloat162float(g_mbf[p1][b0]);
        float n1 = __bfloat162float(g_mbf[p1][b0 + 1]);
        part1 += d[j][2] * n0 + d[j][3] * n1;
    }
    part0 += __shfl_xor_sync(0xffffffffu, part0, 1);
    part0 += __shfl_xor_sync(0xffffffffu, part0, 2);
    part1 += __shfl_xor_sync(0xffffffffu, part1, 1);
    part1 += __shfl_xor_sync(0xffffffffu, part1, 2);
    if (lr == 0) {
        g_part[kk][nt * 2 + wn][p0] = part0;
        g_part[kk][nt * 2 + wn][p1] = part1;
    }
}

// ---------------- kernel 4: finish -> W'[a] = +-z/nm, cst' ---------------
__global__ void k_finish() {
    const int kk = blockIdx.x;
    const int tid = threadIdx.x;   // 256
    float sS = 0.f, sD = 0.f;
    for (int a = tid; a < NPTS; a += 256) {
        float row = 0.f;
        #pragma unroll
        for (int bj = 0; bj < 12; bj++) row += g_rowP[kk][bj][a];
        // W'[a] = (col - row)/nm;  col-row = +z[a] (a<384), -z[a-384] (a>=384)
        g_W[kk][a] = (a < NHALF) ? (INV_NM * g_z[kk][a])
                                 : (-INV_NM * g_z[kk][a - NHALF]);
        sS += row;
        sD += g_diag[kk][a];
    }
    __shared__ float sm[2][8];
    float r1 = warpred(sS), r2 = warpred(sD);
    if ((tid & 31) == 0) { sm[0][tid >> 5] = r1; sm[1][tid >> 5] = r2; }
    __syncthreads();
    if (tid == 0) {
        float S = 0.f, D = 0.f;
        #pragma unroll
        for (int w = 0; w < 8; w++) { S += sm[0][w]; D += sm[1][w]; }
        // cst' = S*(1/nn - C1/4) - Dt/nn = S*CS - Dt*INV_NN  (CS analytic, no cancellation)
        g_cst[kk] = S * CS - D * INV_NN;
    }
}

// ---------------- kernel 5: phase 2 per-slot combine ---------------------
// Ub = (C1/4)*T + sum_{a in A} W'[a] + C4*cross + cst'
__global__ void k_phase2(const int* __restrict__ perms, float* __restrict__ out) {
    const int p = blockIdx.x;          // 201
    const int tid = threadIdx.x;       // 128
    __shared__ int pa[NHALF], pb[NHALF];
    __shared__ float sm[2][4];
    const bool ident = (p == NPER);

    for (int j = tid; j < NHALF; j += 128) {
        pa[j] = ident ? j : perms[p * NPTS + j];
        pb[j] = ident ? (NHALF + j) : perms[p * NPTS + NHALF + j];
    }
    __syncthreads();

    for (int kk = 0; kk < NKER; kk++) {
        const float* __restrict__ W = g_W[kk];
        const __nv_bfloat16* __restrict__ Kh = g_Khi[kk];
        const __nv_bfloat16* __restrict__ Km = g_Kmd[kk];
        const __nv_bfloat16* __restrict__ Kl = g_Klo[kk];
        float t1 = 0.f, cr = 0.f;
        #pragma unroll
        for (int j = tid; j < NHALF; j += 128) {
            int a = pa[j];
            t1 += W[a];
            size_t o = (size_t)a * NPTS + pb[j];
            cr += __bfloat162float(Kh[o]) + __bfloat162float(Km[o])
                + __bfloat162float(Kl[o]);
        }
        if (tid < 12) t1 += C14 * g_part[kk][tid][p];
        float r1 = warpred(t1), r2 = warpred(cr);
        if ((tid & 31) == 0) { sm[0][tid >> 5] = r1; sm[1][tid >> 5] = r2; }
        __syncthreads();
        if (tid == 0) {
            float T1 = sm[0][0] + sm[0][1] + sm[0][2] + sm[0][3];
            float CR = sm[1][0] + sm[1][1] + sm[1][2] + sm[1][3];
            float Ub = T1 + C4 * CR + g_cst[kk];
            int idx = ident ? (kk * (NPER + 1)) : (kk * (NPER + 1) + 1 + p);
            out[idx] = Ub;
        }
        __syncthreads();
    }
}

// ---------------- launch ----------------
extern "C" void kernel_launch(void* const* d_in, const int* in_sizes, int n_in,
                              void* d_out, int out_size) {
    const float* X     = (const float*)d_in[0];
    const float* Y     = (const float*)d_in[1];
    const float* bw    = (const float*)d_in[2];
    const int*   perms = (const int*)d_in[3];
    float* out = (float*)d_out;

    k_maskset<<<NSLOT, NPTS>>>(perms);
    k_pairK<<<dim3(12, 12), 256>>>(X, Y, bw);
    k_mma<<<dim3(6, 4, NKER), 256>>>();
    k_finish<<<NKER, 256>>>();
    k_phase2<<<NSLOT, 128>>>(perms, out);
}

// round 9
// speedup vs baseline: 1.9832x; 1.9832x over previous
#include <cuda_runtime.h>
#include <cuda_bf16.h>
#include <math.h>
#include <cstdint>

#define NPTS  768
#define NHALF 384
#define DDIM  64
#define NPER  200
#define NKER  4
#define NSLOT 202     // 200 perms + identity(200) + all-ones(201)
#define PSLOTS 256    // padded p dimension (4 tiles of 64)

#define INV_NN (1.0f/147072.0f)    // 384*383
#define INV_NM (1.0f/147456.0f)    // 384*384
#define C1 (2.0f*INV_NN + 2.0f*INV_NM)
#define C14 (0.25f*C1)
#define C4 (2.0f*INV_NM)
// 0.5*(1/nn - 1/nm), computed analytically in double (no cancellation)
#define CS ((float)(0.5*(1.0/147072.0 - 1.0/147456.0)))

// ---------------- scratch (device globals; zero-initialized) -------------
__device__ __nv_bfloat16 g_Khi[NKER][NPTS * NPTS];   // 4.5 MB
__device__ __nv_bfloat16 g_Kmd[NKER][NPTS * NPTS];   // 4.5 MB
__device__ __nv_bfloat16 g_mbf[PSLOTS][NPTS];        // signed mask rows
__device__ float g_z[NKER][NHALF];                   // K[384+i][i] (pre-zero value)
__device__ float g_DtP[NKER][12];                    // diag partials per diag block
__device__ float g_part[NKER][24][PSLOTS];           // T partials (2 ksplit x 12 subtiles)

// ---------------- helpers ----------------
__device__ __forceinline__ float warpred(float v) {
    #pragma unroll
    for (int o = 16; o > 0; o >>= 1) v += __shfl_down_sync(0xffffffffu, v, o);
    return v;
}

__device__ __forceinline__ uint32_t s2u(const void* p) {
    uint32_t r;
    asm("{ .reg .u64 t; cvta.to.shared.u64 t, %1; cvt.u32.u64 %0, t; }"
        : "=r"(r) : "l"(p));
    return r;
}

// ---------------- kernel 1: pairwise kernel matrices (bf16 hi/md) --------
__global__ void __launch_bounds__(256) k_pairK(const float* __restrict__ X,
                                               const float* __restrict__ Y,
                                               const float* __restrict__ bw) {
    __shared__ float Zi[64][65];
    __shared__ float Zj[64][65];
    __shared__ float sqi[64], sqj[64];
    __shared__ float dsh[16][NKER];
    const int i0 = blockIdx.y * 64, j0 = blockIdx.x * 64;
    const int tid = threadIdx.x;

    for (int idx = tid; idx < 64 * 64; idx += 256) {
        int r = idx >> 6, d = idx & 63;
        int gi = i0 + r;
        Zi[r][d] = (gi < NHALF) ? X[gi * DDIM + d] : Y[(gi - NHALF) * DDIM + d];
        int gj = j0 + r;
        Zj[r][d] = (gj < NHALF) ? X[gj * DDIM + d] : Y[(gj - NHALF) * DDIM + d];
    }
    __syncthreads();

    if (tid < 64) {
        float s = 0.f;
        #pragma unroll
        for (int d = 0; d < 64; d++) { float v = Zi[tid][d]; s += v * v; }
        sqi[tid] = s;
    } else if (tid < 128) {
        int r = tid - 64;
        float s = 0.f;
        #pragma unroll
        for (int d = 0; d < 64; d++) { float v = Zj[r][d]; s += v * v; }
        sqj[r] = s;
    }
    __syncthreads();

    const int tx = tid & 15, ty = tid >> 4;
    float acc[4][4] = {};
    #pragma unroll 4
    for (int d = 0; d < 64; d++) {
        float a0 = Zi[ty * 4 + 0][d], a1 = Zi[ty * 4 + 1][d];
        float a2 = Zi[ty * 4 + 2][d], a3 = Zi[ty * 4 + 3][d];
        float b0 = Zj[tx * 4 + 0][d], b1 = Zj[tx * 4 + 1][d];
        float b2 = Zj[tx * 4 + 2][d], b3 = Zj[tx * 4 + 3][d];
        acc[0][0] += a0 * b0; acc[0][1] += a0 * b1; acc[0][2] += a0 * b2; acc[0][3] += a0 * b3;
        acc[1][0] += a1 * b0; acc[1][1] += a1 * b1; acc[1][2] += a1 * b2; acc[1][3] += a1 * b3;
        acc[2][0] += a2 * b0; acc[2][1] += a2 * b1; acc[2][2] += a2 * b2; acc[2][3] += a2 * b3;
        acc[3][0] += a3 * b0; acc[3][1] += a3 * b1; acc[3][2] += a3 * b2; acc[3][3] += a3 * b3;
    }

    const float ig0 = 1.f / (bw[0] * bw[0]);
    const float il1 = 1.f / bw[1];
    const float ig2 = 1.f / (bw[2] * bw[2]);
    const float il3 = 1.f / bw[3];

    float dsum[NKER] = {0.f, 0.f, 0.f, 0.f};

    #pragma unroll
    for (int ii = 0; ii < 4; ii++) {
        const int gi = i0 + ty * 4 + ii;
        const float si = sqi[ty * 4 + ii];
        union { __nv_bfloat16 b[4]; uint2 u; } hb[NKER], mb[NKER];
        #pragma unroll
        for (int jj = 0; jj < 4; jj++) {
            const int gj = j0 + tx * 4 + jj;
            float d2 = si + sqj[tx * 4 + jj] - 2.f * acc[ii][jj];
            d2 = fmaxf(d2, 0.f);
            float dist = sqrtf(d2 + 1e-12f);
            float dd = dist * dist;
            float kv[NKER];
            kv[0] = __expf(-dd * ig0);
            kv[1] = __expf(-dist * il1);
            kv[2] = __expf(-dd * ig2);
            kv[3] = __expf(-dist * il3);
            if (gi == gj + NHALF) {
                g_z[0][gj] = kv[0]; g_z[1][gj] = kv[1];
                g_z[2][gj] = kv[2]; g_z[3][gj] = kv[3];
            }
            if (gi == gj) {
                dsum[0] += kv[0]; dsum[1] += kv[1];
                dsum[2] += kv[2]; dsum[3] += kv[3];
            }
            if (gi < NHALF && gj == gi + NHALF) {
                kv[0] = kv[1] = kv[2] = kv[3] = 0.f;
            }
            #pragma unroll
            for (int k = 0; k < NKER; k++) {
                __nv_bfloat16 h = __float2bfloat16(kv[k]);
                float r1 = kv[k] - __bfloat162float(h);
                hb[k].b[jj] = h;
                mb[k].b[jj] = __float2bfloat16(r1);
            }
        }
        const size_t base = (size_t)gi * NPTS + j0 + tx * 4;
        #pragma unroll
        for (int k = 0; k < NKER; k++) {
            *(uint2*)&g_Khi[k][base] = hb[k].u;
            *(uint2*)&g_Kmd[k][base] = mb[k].u;
        }
    }

    // diag blocks: deterministic block-reduce of diagonal sums
    if (i0 == j0) {
        if (tx == ty) {
            #pragma unroll
            for (int k = 0; k < NKER; k++) dsh[ty][k] = dsum[k];
        }
        __syncthreads();
        if (tid == 0) {
            #pragma unroll
            for (int k = 0; k < NKER; k++) {
                float s = 0.f;
                #pragma unroll
                for (int r = 0; r < 16; r++) s += dsh[r][k];
                g_DtP[k][blockIdx.x] = s;
            }
        }
    }
}

// ---------------- kernel 2: signed mask rows ------------------------------
// p<200: perm p (+1 on A, -1 on B). p=200: identity. p=201: all +1 (S probe).
__global__ void k_maskset(const int* __restrict__ perms) {
    const int p = blockIdx.x;          // 202
    const int j = threadIdx.x;         // 768
    if (p < NPER) {
        const __nv_bfloat16 v = __float2bfloat16(j < NHALF ? 1.f : -1.f);
        g_mbf[p][perms[p * NPTS + j]] = v;
    } else if (p == NPER) {
        g_mbf[p][j] = __float2bfloat16(j < NHALF ? 1.f : -1.f);
    } else {
        g_mbf[p][j] = __float2bfloat16(1.f);
    }
}

// ---------------- kernel 3: mma.sync signed GEMM -> T partials -----------
// grid (6 n-tiles, 4 p-tiles, kk*2+ksplit); 256 threads (8 warps: 4m x 2n).
// Each CTA: m=64 p-slots, n=128 K-rows, k=768 over ONE split matrix.
__global__ void __launch_bounds__(256) k_mma() {
    __shared__ __align__(16) unsigned char As[2][64 * 128];    // 16 KB
    __shared__ __align__(16) unsigned char Bs[2][128 * 128];   // 32 KB
    const int nt = blockIdx.x, pt = blockIdx.y;
    const int kk = blockIdx.z >> 1, ks = blockIdx.z & 1;
    const int tid = threadIdx.x, w = tid >> 5, lane = tid & 31;
    const int wm = w & 3, wn = w >> 2;
    const uint32_t aBase = s2u(&As[0][0]);
    const uint32_t bBase = s2u(&Bs[0][0]);
    const __nv_bfloat16* __restrict__ KP = ks ? g_Kmd[kk] : g_Khi[kk];

    float d[8][4] = {};

    auto load = [&](int ch, int buf) {
        const int a0 = ch * 64;
        #pragma unroll 2
        for (int idx = tid; idx < 512; idx += 256) {        // A: 64 rows x 128B
            int r = idx >> 3, c = idx & 7;
            uint4 v = *(const uint4*)&g_mbf[pt * 64 + r][a0 + c * 8];
            *(uint4*)&As[buf][r * 128 + ((c ^ (r & 7)) << 4)] = v;
        }
        #pragma unroll 4
        for (int idx = tid; idx < 1024; idx += 256) {       // B: 128 rows x 128B
            int r = idx >> 3, c = idx & 7;
            uint4 v = *(const uint4*)&KP[(size_t)(nt * 128 + r) * NPTS + a0 + c * 8];
            *(uint4*)&Bs[buf][r * 128 + ((c ^ (r & 7)) << 4)] = v;
        }
    };

    load(0, 0);
    __syncthreads();
    for (int ch = 0; ch < 12; ch++) {
        const int buf = ch & 1;
        if (ch + 1 < 12) load(ch + 1, buf ^ 1);
        #pragma unroll
        for (int ksq = 0; ksq < 4; ksq++) {
            uint32_t a[4];
            {
                int r = wm * 16 + (lane & 15);
                int c = ksq * 2 + (lane >> 4);
                uint32_t addr = aBase + buf * 8192 + r * 128 + ((c ^ (r & 7)) << 4);
                asm volatile("ldmatrix.sync.aligned.m8n8.x4.shared.b16 {%0,%1,%2,%3}, [%4];"
                             : "=r"(a[0]), "=r"(a[1]), "=r"(a[2]), "=r"(a[3]) : "r"(addr));
            }
            #pragma unroll
            for (int j = 0; j < 8; j++) {
                uint32_t b[2];
                int r = wn * 64 + j * 8 + (lane & 7);
                int c = ksq * 2 + ((lane >> 3) & 1);
                uint32_t addr = bBase + buf * 16384 + r * 128 + ((c ^ (r & 7)) << 4);
                asm volatile("ldmatrix.sync.aligned.m8n8.x2.shared.b16 {%0,%1}, [%2];"
                             : "=r"(b[0]), "=r"(b[1]) : "r"(addr));
                asm volatile("mma.sync.aligned.m16n8k16.row.col.f32.bf16.bf16.f32 "
                             "{%0,%1,%2,%3}, {%4,%5,%6,%7}, {%8,%9}, {%0,%1,%2,%3};"
                             : "+f"(d[j][0]), "+f"(d[j][1]), "+f"(d[j][2]), "+f"(d[j][3])
                             : "r"(a[0]), "r"(a[1]), "r"(a[2]), "r"(a[3]),
                               "r"(b[0]), "r"(b[1]));
            }
        }
        __syncthreads();
    }

    // epilogue: partial T[p] = sum_b s[p][b] * D'[p][b]
    const int lq = lane >> 2, lr = lane & 3;
    const int p0 = pt * 64 + wm * 16 + lq;
    const int p1 = p0 + 8;
    float part0 = 0.f, part1 = 0.f;
    #pragma unroll
    for (int j = 0; j < 8; j++) {
        int b0 = nt * 128 + wn * 64 + j * 8 + lr * 2;
        float m0 = __bfloat162float(g_mbf[p0][b0]);
        float m1 = __bfloat162float(g_mbf[p0][b0 + 1]);
        part0 += d[j][0] * m0 + d[j][1] * m1;
        float n0 = __bfloat162float(g_mbf[p1][b0]);
        float n1 = __bfloat162float(g_mbf[p1][b0 + 1]);
        part1 += d[j][2] * n0 + d[j][3] * n1;
    }
    part0 += __shfl_xor_sync(0xffffffffu, part0, 1);
    part0 += __shfl_xor_sync(0xffffffffu, part0, 2);
    part1 += __shfl_xor_sync(0xffffffffu, part1, 1);
    part1 += __shfl_xor_sync(0xffffffffu, part1, 2);
    if (lr == 0) {
        const int sub = ks * 12 + nt * 2 + wn;
        g_part[kk][sub][p0] = part0;
        g_part[kk][sub][p1] = part1;
    }
}

// ---------------- kernel 4: phase 2 per-slot combine ---------------------
// Ub = (C1/4)*T + sum_{a in A} (+-z[a])/nm + C4*cross + (S*CS - Dt/nn)
// S = T of the all-ones slot (201); Dt from g_DtP.
__global__ void k_phase2(const int* __restrict__ perms, float* __restrict__ out) {
    const int p = blockIdx.x;          // 201
    const int tid = threadIdx.x;       // 128
    __shared__ int pa[NHALF], pb[NHALF];
    __shared__ float sm[3][4];
    const bool ident = (p == NPER);

    for (int j = tid; j < NHALF; j += 128) {
        pa[j] = ident ? j : perms[p * NPTS + j];
        pb[j] = ident ? (NHALF + j) : perms[p * NPTS + NHALF + j];
    }
    __syncthreads();

    for (int kk = 0; kk < NKER; kk++) {
        const float* __restrict__ Zc = g_z[kk];
        const __nv_bfloat16* __restrict__ Kh = g_Khi[kk];
        const __nv_bfloat16* __restrict__ Km = g_Kmd[kk];
        float t1 = 0.f, cr = 0.f, aux = 0.f;
        #pragma unroll
        for (int j = tid; j < NHALF; j += 128) {
            int a = pa[j];
            t1 += (a < NHALF) ? (INV_NM * Zc[a]) : (-INV_NM * Zc[a - NHALF]);
            size_t o = (size_t)a * NPTS + pb[j];
            cr += __bfloat162float(Kh[o]) + __bfloat162float(Km[o]);
        }
        if (tid < 24) {
            t1 += C14 * g_part[kk][tid][p];
            aux += CS * g_part[kk][tid][201];      // S*CS partials
        }
        if (tid >= 32 && tid < 44)
            aux -= INV_NN * g_DtP[kk][tid - 32];   // -Dt/nn partials
        float r1 = warpred(t1), r2 = warpred(cr), r3 = warpred(aux);
        if ((tid & 31) == 0) {
            sm[0][tid >> 5] = r1; sm[1][tid >> 5] = r2; sm[2][tid >> 5] = r3;
        }
        __syncthreads();
        if (tid == 0) {
            float T1 = sm[0][0] + sm[0][1] + sm[0][2] + sm[0][3];
            float CR = sm[1][0] + sm[1][1] + sm[1][2] + sm[1][3];
            float AX = sm[2][0] + sm[2][1] + sm[2][2] + sm[2][3];
            float Ub = T1 + C4 * CR + AX;
            int idx = ident ? (kk * (NPER + 1)) : (kk * (NPER + 1) + 1 + p);
            out[idx] = Ub;
        }
        __syncthreads();
    }
}

// ---------------- launch ----------------
extern "C" void kernel_launch(void* const* d_in, const int* in_sizes, int n_in,
                              void* d_out, int out_size) {
    const float* X     = (const float*)d_in[0];
    const float* Y     = (const float*)d_in[1];
    const float* bw    = (const float*)d_in[2];
    const int*   perms = (const int*)d_in[3];
    float* out = (float*)d_out;

    k_maskset<<<NSLOT, NPTS>>>(perms);
    k_pairK<<<dim3(12, 12), 256>>>(X, Y, bw);
    k_mma<<<dim3(6, 4, 8), 256>>>();
    k_phase2<<<NPER + 1, 128>>>(perms, out);
}

// round 10
// speedup vs baseline: 2.0918x; 1.0548x over previous
#include <cuda_runtime.h>
#include <cuda_bf16.h>
#include <math.h>
#include <cstdint>

#define NPTS  768
#define NHALF 384
#define DDIM  64
#define NPER  200
#define NKER  4
#define NSLOT 202     // 200 perms + identity(200) + all-ones(201)
#define PSLOTS 256    // padded p dimension (4 tiles of 64)

#define INV_NN (1.0f/147072.0f)    // 384*383
#define INV_NM (1.0f/147456.0f)    // 384*384
#define C1 (2.0f*INV_NN + 2.0f*INV_NM)
#define C14 (0.25f*C1)
#define C4 (2.0f*INV_NM)
// 0.5*(1/nn - 1/nm), analytic (no cancellation)
#define CS ((float)(0.5*(1.0/147072.0 - 1.0/147456.0)))

// ---------------- scratch (device globals; zero-initialized) -------------
__device__ __nv_bfloat16 g_Khi[NKER][NPTS * NPTS];   // 4.5 MB
__device__ __nv_bfloat16 g_Kmd[NKER][NPTS * NPTS];   // 4.5 MB
__device__ uint32_t      g_Kpk[NKER][NPTS * NPTS];   // 9 MB (hi|md packed)
__device__ __nv_bfloat16 g_mbf[PSLOTS][NPTS];        // signed mask rows
__device__ float g_z[NKER][NHALF];                   // K[384+i][i] (pre-zero value)
__device__ float g_DtP[NKER][12];                    // diag partials per diag block
__device__ float g_part[NKER][24][PSLOTS];           // T partials (2 ksplit x 12 subtiles)

// ---------------- helpers ----------------
__device__ __forceinline__ float warpred(float v) {
    #pragma unroll
    for (int o = 16; o > 0; o >>= 1) v += __shfl_down_sync(0xffffffffu, v, o);
    return v;
}

__device__ __forceinline__ uint32_t s2u(const void* p) {
    uint32_t r;
    asm("{ .reg .u64 t; cvta.to.shared.u64 t, %1; cvt.u32.u64 %0, t; }"
        : "=r"(r) : "l"(p));
    return r;
}

// ---------------- kernel 1: pairK (blocks 0..143) + maskset (144..345) ---
__global__ void __launch_bounds__(256) k_pairmask(const float* __restrict__ X,
                                                  const float* __restrict__ Y,
                                                  const float* __restrict__ bw,
                                                  const int* __restrict__ perms) {
    const int blk = blockIdx.x;
    const int tid = threadIdx.x;

    if (blk >= 144) {                       // ---- mask part ----
        const int p = blk - 144;            // 0..201
        #pragma unroll
        for (int j = tid; j < NPTS; j += 256) {
            if (p < NPER) {
                g_mbf[p][perms[p * NPTS + j]] = __float2bfloat16(j < NHALF ? 1.f : -1.f);
            } else if (p == NPER) {
                g_mbf[p][j] = __float2bfloat16(j < NHALF ? 1.f : -1.f);
            } else {
                g_mbf[p][j] = __float2bfloat16(1.f);
            }
        }
        return;
    }

    // ---- pairK part ----
    __shared__ float Zi[64][65];
    __shared__ float Zj[64][65];
    __shared__ float sqi[64], sqj[64];
    __shared__ float dsh[16][NKER];
    const int bi = blk / 12, bj = blk % 12;
    const int i0 = bi * 64, j0 = bj * 64;

    for (int idx = tid; idx < 64 * 64; idx += 256) {
        int r = idx >> 6, d = idx & 63;
        int gi = i0 + r;
        Zi[r][d] = (gi < NHALF) ? X[gi * DDIM + d] : Y[(gi - NHALF) * DDIM + d];
        int gj = j0 + r;
        Zj[r][d] = (gj < NHALF) ? X[gj * DDIM + d] : Y[(gj - NHALF) * DDIM + d];
    }
    __syncthreads();

    if (tid < 64) {
        float s = 0.f;
        #pragma unroll
        for (int d = 0; d < 64; d++) { float v = Zi[tid][d]; s += v * v; }
        sqi[tid] = s;
    } else if (tid < 128) {
        int r = tid - 64;
        float s = 0.f;
        #pragma unroll
        for (int d = 0; d < 64; d++) { float v = Zj[r][d]; s += v * v; }
        sqj[r] = s;
    }
    __syncthreads();

    const int tx = tid & 15, ty = tid >> 4;
    float acc[4][4] = {};
    #pragma unroll 4
    for (int d = 0; d < 64; d++) {
        float a0 = Zi[ty * 4 + 0][d], a1 = Zi[ty * 4 + 1][d];
        float a2 = Zi[ty * 4 + 2][d], a3 = Zi[ty * 4 + 3][d];
        float b0 = Zj[tx * 4 + 0][d], b1 = Zj[tx * 4 + 1][d];
        float b2 = Zj[tx * 4 + 2][d], b3 = Zj[tx * 4 + 3][d];
        acc[0][0] += a0 * b0; acc[0][1] += a0 * b1; acc[0][2] += a0 * b2; acc[0][3] += a0 * b3;
        acc[1][0] += a1 * b0; acc[1][1] += a1 * b1; acc[1][2] += a1 * b2; acc[1][3] += a1 * b3;
        acc[2][0] += a2 * b0; acc[2][1] += a2 * b1; acc[2][2] += a2 * b2; acc[2][3] += a2 * b3;
        acc[3][0] += a3 * b0; acc[3][1] += a3 * b1; acc[3][2] += a3 * b2; acc[3][3] += a3 * b3;
    }

    const float ig0 = 1.f / (bw[0] * bw[0]);
    const float il1 = 1.f / bw[1];
    const float ig2 = 1.f / (bw[2] * bw[2]);
    const float il3 = 1.f / bw[3];

    float dsum[NKER] = {0.f, 0.f, 0.f, 0.f};

    #pragma unroll
    for (int ii = 0; ii < 4; ii++) {
        const int gi = i0 + ty * 4 + ii;
        const float si = sqi[ty * 4 + ii];
        union { __nv_bfloat16 b[4]; uint2 u; } hb[NKER], mb[NKER];
        union { uint32_t w[4]; uint4 u; } pk[NKER];
        #pragma unroll
        for (int jj = 0; jj < 4; jj++) {
            const int gj = j0 + tx * 4 + jj;
            float d2 = si + sqj[tx * 4 + jj] - 2.f * acc[ii][jj];
            d2 = fmaxf(d2, 0.f);
            float dist = sqrtf(d2 + 1e-12f);
            float dd = dist * dist;
            float kv[NKER];
            kv[0] = __expf(-dd * ig0);
            kv[1] = __expf(-dist * il1);
            kv[2] = __expf(-dd * ig2);
            kv[3] = __expf(-dist * il3);
            if (gi == gj + NHALF) {
                g_z[0][gj] = kv[0]; g_z[1][gj] = kv[1];
                g_z[2][gj] = kv[2]; g_z[3][gj] = kv[3];
            }
            if (gi == gj) {
                dsum[0] += kv[0]; dsum[1] += kv[1];
                dsum[2] += kv[2]; dsum[3] += kv[3];
            }
            if (gi < NHALF && gj == gi + NHALF) {
                kv[0] = kv[1] = kv[2] = kv[3] = 0.f;
            }
            #pragma unroll
            for (int k = 0; k < NKER; k++) {
                __nv_bfloat16 h = __float2bfloat16(kv[k]);
                float r1 = kv[k] - __bfloat162float(h);
                __nv_bfloat16 m = __float2bfloat16(r1);
                hb[k].b[jj] = h;
                mb[k].b[jj] = m;
                __nv_bfloat162 pr(h, m);           // x = hi (low 16), y = md
                pk[k].w[jj] = *(uint32_t*)&pr;
            }
        }
        const size_t base = (size_t)gi * NPTS + j0 + tx * 4;
        #pragma unroll
        for (int k = 0; k < NKER; k++) {
            *(uint2*)&g_Khi[k][base] = hb[k].u;
            *(uint2*)&g_Kmd[k][base] = mb[k].u;
            *(uint4*)&g_Kpk[k][base] = pk[k].u;
        }
    }

    // diag blocks: deterministic block-reduce of diagonal sums
    if (i0 == j0) {
        if (tx == ty) {
            #pragma unroll
            for (int k = 0; k < NKER; k++) dsh[ty][k] = dsum[k];
        }
        __syncthreads();
        if (tid == 0) {
            #pragma unroll
            for (int k = 0; k < NKER; k++) {
                float s = 0.f;
                #pragma unroll
                for (int r = 0; r < 16; r++) s += dsh[r][k];
                g_DtP[k][bi] = s;
            }
        }
    }
}

// ---------------- kernel 2: mma.sync signed GEMM -> T partials -----------
// grid (6 n-tiles, 4 p-tiles, kk*2+ksplit); 256 threads (8 warps: 4m x 2n).
__global__ void __launch_bounds__(256) k_mma() {
    __shared__ __align__(16) unsigned char As[2][64 * 128];    // 16 KB
    __shared__ __align__(16) unsigned char Bs[2][128 * 128];   // 32 KB
    const int nt = blockIdx.x, pt = blockIdx.y;
    const int kk = blockIdx.z >> 1, ks = blockIdx.z & 1;
    const int tid = threadIdx.x, w = tid >> 5, lane = tid & 31;
    const int wm = w & 3, wn = w >> 2;
    const uint32_t aBase = s2u(&As[0][0]);
    const uint32_t bBase = s2u(&Bs[0][0]);
    const __nv_bfloat16* __restrict__ KP = ks ? g_Kmd[kk] : g_Khi[kk];

    float d[8][4] = {};

    auto load = [&](int ch, int buf) {
        const int a0 = ch * 64;
        #pragma unroll 2
        for (int idx = tid; idx < 512; idx += 256) {        // A: 64 rows x 128B
            int r = idx >> 3, c = idx & 7;
            uint4 v = *(const uint4*)&g_mbf[pt * 64 + r][a0 + c * 8];
            *(uint4*)&As[buf][r * 128 + ((c ^ (r & 7)) << 4)] = v;
        }
        #pragma unroll 4
        for (int idx = tid; idx < 1024; idx += 256) {       // B: 128 rows x 128B
            int r = idx >> 3, c = idx & 7;
            uint4 v = *(const uint4*)&KP[(size_t)(nt * 128 + r) * NPTS + a0 + c * 8];
            *(uint4*)&Bs[buf][r * 128 + ((c ^ (r & 7)) << 4)] = v;
        }
    };

    load(0, 0);
    __syncthreads();
    for (int ch = 0; ch < 12; ch++) {
        const int buf = ch & 1;
        if (ch + 1 < 12) load(ch + 1, buf ^ 1);
        #pragma unroll
        for (int ksq = 0; ksq < 4; ksq++) {
            uint32_t a[4];
            {
                int r = wm * 16 + (lane & 15);
                int c = ksq * 2 + (lane >> 4);
                uint32_t addr = aBase + buf * 8192 + r * 128 + ((c ^ (r & 7)) << 4);
                asm volatile("ldmatrix.sync.aligned.m8n8.x4.shared.b16 {%0,%1,%2,%3}, [%4];"
                             : "=r"(a[0]), "=r"(a[1]), "=r"(a[2]), "=r"(a[3]) : "r"(addr));
            }
            #pragma unroll
            for (int j = 0; j < 8; j++) {
                uint32_t b[2];
                int r = wn * 64 + j * 8 + (lane & 7);
                int c = ksq * 2 + ((lane >> 3) & 1);
                uint32_t addr = bBase + buf * 16384 + r * 128 + ((c ^ (r & 7)) << 4);
                asm volatile("ldmatrix.sync.aligned.m8n8.x2.shared.b16 {%0,%1}, [%2];"
                             : "=r"(b[0]), "=r"(b[1]) : "r"(addr));
                asm volatile("mma.sync.aligned.m16n8k16.row.col.f32.bf16.bf16.f32 "
                             "{%0,%1,%2,%3}, {%4,%5,%6,%7}, {%8,%9}, {%0,%1,%2,%3};"
                             : "+f"(d[j][0]), "+f"(d[j][1]), "+f"(d[j][2]), "+f"(d[j][3])
                             : "r"(a[0]), "r"(a[1]), "r"(a[2]), "r"(a[3]),
                               "r"(b[0]), "r"(b[1]));
            }
        }
        __syncthreads();
    }

    // epilogue: partial T[p] = sum_b s[p][b] * D'[p][b]
    const int lq = lane >> 2, lr = lane & 3;
    const int p0 = pt * 64 + wm * 16 + lq;
    const int p1 = p0 + 8;
    float part0 = 0.f, part1 = 0.f;
    #pragma unroll
    for (int j = 0; j < 8; j++) {
        int b0 = nt * 128 + wn * 64 + j * 8 + lr * 2;
        float m0 = __bfloat162float(g_mbf[p0][b0]);
        float m1 = __bfloat162float(g_mbf[p0][b0 + 1]);
        part0 += d[j][0] * m0 + d[j][1] * m1;
        float n0 = __bfloat162float(g_mbf[p1][b0]);
        float n1 = __bfloat162float(g_mbf[p1][b0 + 1]);
        part1 += d[j][2] * n0 + d[j][3] * n1;
    }
    part0 += __shfl_xor_sync(0xffffffffu, part0, 1);
    part0 += __shfl_xor_sync(0xffffffffu, part0, 2);
    part1 += __shfl_xor_sync(0xffffffffu, part1, 1);
    part1 += __shfl_xor_sync(0xffffffffu, part1, 2);
    if (lr == 0) {
        const int sub = ks * 12 + nt * 2 + wn;
        g_part[kk][sub][p0] = part0;
        g_part[kk][sub][p1] = part1;
    }
}

// ---------------- kernel 3: phase 2 per-(slot, kernel) combine -----------
// Ub = (C1/4)*T + sum_{a in A} (+-z[a])/nm + C4*cross + (S*CS - Dt/nn)
__global__ void __launch_bounds__(128) k_phase2(const int* __restrict__ perms,
                                                float* __restrict__ out) {
    const int p = blockIdx.x;          // 0..200
    const int kk = blockIdx.y;
    const int tid = threadIdx.x;       // 128
    __shared__ float sm[3][4];
    const bool ident = (p == NPER);

    const uint32_t* __restrict__ Kp = g_Kpk[kk];
    const float* __restrict__ Zc = g_z[kk];

    float t1 = 0.f, cr = 0.f, aux = 0.f;
    #pragma unroll
    for (int it = 0; it < 3; it++) {
        int j = tid + it * 128;
        int a = ident ? j : __ldg(&perms[p * NPTS + j]);
        int b = ident ? (NHALF + j) : __ldg(&perms[p * NPTS + NHALF + j]);
        t1 += (a < NHALF) ? (INV_NM * Zc[a]) : (-INV_NM * Zc[a - NHALF]);
        uint32_t w = __ldg(&Kp[a * NPTS + b]);
        __nv_bfloat162 v = *reinterpret_cast<__nv_bfloat162*>(&w);
        cr += __bfloat162float(v.x) + __bfloat162float(v.y);
    }
    if (tid < 24) {
        t1 += C14 * g_part[kk][tid][p];
        aux += CS * g_part[kk][tid][201];          // S*CS partials
    }
    if (tid >= 32 && tid < 44)
        aux -= INV_NN * g_DtP[kk][tid - 32];       // -Dt/nn partials

    float r1 = warpred(t1), r2 = warpred(cr), r3 = warpred(aux);
    if ((tid & 31) == 0) {
        sm[0][tid >> 5] = r1; sm[1][tid >> 5] = r2; sm[2][tid >> 5] = r3;
    }
    __syncthreads();
    if (tid == 0) {
        float T1 = sm[0][0] + sm[0][1] + sm[0][2] + sm[0][3];
        float CR = sm[1][0] + sm[1][1] + sm[1][2] + sm[1][3];
        float AX = sm[2][0] + sm[2][1] + sm[2][2] + sm[2][3];
        float Ub = T1 + C4 * CR + AX;
        int idx = ident ? (kk * (NPER + 1)) : (kk * (NPER + 1) + 1 + p);
        out[idx] = Ub;
    }
}

// ---------------- launch ----------------
extern "C" void kernel_launch(void* const* d_in, const int* in_sizes, int n_in,
                              void* d_out, int out_size) {
    const float* X     = (const float*)d_in[0];
    const float* Y     = (const float*)d_in[1];
    const float* bw    = (const float*)d_in[2];
    const int*   perms = (const int*)d_in[3];
    float* out = (float*)d_out;

    k_pairmask<<<144 + NSLOT, 256>>>(X, Y, bw, perms);
    k_mma<<<dim3(6, 4, 8), 256>>>();
    k_phase2<<<dim3(NPER + 1, NKER), 128>>>(perms, out);
}

// round 11
// speedup vs baseline: 2.2023x; 1.0528x over previous
#include <cuda_runtime.h>
#include <cuda_bf16.h>
#include <math.h>
#include <cstdint>

#define NPTS  768
#define NHALF 384
#define DDIM  64
#define NPER  200
#define NKER  4
#define NSLOT 202     // 200 perms + identity(200) + all-ones(201)
#define PSLOTS 256    // padded p dimension (4 tiles of 64)
#define NTRI  300     // 24*25/2 triangle blocks of 32x32

#define INV_NN (1.0f/147072.0f)    // 384*383
#define INV_NM (1.0f/147456.0f)    // 384*384
#define C1 (2.0f*INV_NN + 2.0f*INV_NM)
#define C14 (0.25f*C1)
#define C4 (2.0f*INV_NM)
// 0.5*(1/nn - 1/nm), analytic (no cancellation)
#define CS ((float)(0.5*(1.0/147072.0 - 1.0/147456.0)))

// ---------------- scratch (device globals; zero-initialized) -------------
__device__ __nv_bfloat16 g_Khi[NKER][NPTS * NPTS];   // 4.5 MB
__device__ __nv_bfloat16 g_Kmd[NKER][NPTS * NPTS];   // 4.5 MB
__device__ uint32_t      g_Kpk[NKER][NPTS * NPTS];   // 9 MB (hi|md packed)
__device__ __nv_bfloat16 g_mbf[PSLOTS][NPTS];        // signed mask rows
__device__ float g_z[NKER][NHALF];                   // K[i][384+i] pre-zero value
__device__ float g_DtP[NKER][24];                    // diag partials per diag block
__device__ float g_part[NKER][24][PSLOTS];           // T partials (2 ksplit x 12 subtiles)

// ---------------- helpers ----------------
__device__ __forceinline__ float warpred(float v) {
    #pragma unroll
    for (int o = 16; o > 0; o >>= 1) v += __shfl_down_sync(0xffffffffu, v, o);
    return v;
}

__device__ __forceinline__ uint32_t s2u(const void* p) {
    uint32_t r;
    asm("{ .reg .u64 t; cvta.to.shared.u64 t, %1; cvt.u32.u64 %0, t; }"
        : "=r"(r) : "l"(p));
    return r;
}

// ---------------- kernel 1: mask (blocks 0..201) + symmetric pairK -------
// triangle blocks 202..501: (bi,bj), bi<=bj over 24x24 grid of 32x32 tiles.
__global__ void __launch_bounds__(128) k_pairmask(const float* __restrict__ X,
                                                  const float* __restrict__ Y,
                                                  const float* __restrict__ bw,
                                                  const int* __restrict__ perms) {
    const int blk = blockIdx.x;
    const int tid = threadIdx.x;

    if (blk < NSLOT) {                      // ---- mask part ----
        const int p = blk;
        #pragma unroll
        for (int j = tid; j < NPTS; j += 128) {
            if (p < NPER) {
                g_mbf[p][perms[p * NPTS + j]] = __float2bfloat16(j < NHALF ? 1.f : -1.f);
            } else if (p == NPER) {
                g_mbf[p][j] = __float2bfloat16(j < NHALF ? 1.f : -1.f);
            } else {
                g_mbf[p][j] = __float2bfloat16(1.f);
            }
        }
        return;
    }

    // ---- triangle decode ----
    int t = blk - NSLOT, bi = 0;
    while (t >= 24 - bi) { t -= 24 - bi; bi++; }
    const int bj = bi + t;
    const int i0 = bi * 32, j0 = bj * 32;
    const bool diag = (bi == bj);

    __shared__ float Zi[32][65];
    __shared__ float Zj[32][65];
    __shared__ float sq[64];                 // sqi[0..31], sqj[32..63]
    __shared__ uint32_t smT[32][33];         // transpose staging (reused per kernel)
    __shared__ float dsh[4][NKER];

    for (int idx = tid; idx < 32 * 64; idx += 128) {
        int r = idx >> 6, d = idx & 63;
        int gi = i0 + r;
        Zi[r][d] = (gi < NHALF) ? X[gi * DDIM + d] : Y[(gi - NHALF) * DDIM + d];
        int gj = j0 + r;
        Zj[r][d] = (gj < NHALF) ? X[gj * DDIM + d] : Y[(gj - NHALF) * DDIM + d];
    }
    __syncthreads();

    if (tid < 64) {
        const float* src = (tid < 32) ? &Zi[tid][0] : &Zj[tid - 32][0];
        float s = 0.f;
        #pragma unroll
        for (int d = 0; d < 64; d++) { float v = src[d]; s += v * v; }
        sq[tid] = s;
    }
    __syncthreads();

    // 16x8 threads: ty=tid>>3 (16, rows x2), tx=tid&7 (8, cols x4)
    const int tx = tid & 7, ty = tid >> 3;
    float acc[2][4] = {};
    #pragma unroll 4
    for (int d = 0; d < 64; d++) {
        float a0 = Zi[ty * 2 + 0][d], a1 = Zi[ty * 2 + 1][d];
        float b0 = Zj[tx * 4 + 0][d], b1 = Zj[tx * 4 + 1][d];
        float b2 = Zj[tx * 4 + 2][d], b3 = Zj[tx * 4 + 3][d];
        acc[0][0] += a0 * b0; acc[0][1] += a0 * b1; acc[0][2] += a0 * b2; acc[0][3] += a0 * b3;
        acc[1][0] += a1 * b0; acc[1][1] += a1 * b1; acc[1][2] += a1 * b2; acc[1][3] += a1 * b3;
    }

    // distances for the 8 outputs
    float dst[2][4];
    #pragma unroll
    for (int ii = 0; ii < 2; ii++) {
        const float si = sq[ty * 2 + ii];
        #pragma unroll
        for (int jj = 0; jj < 4; jj++) {
            float d2 = si + sq[32 + tx * 4 + jj] - 2.f * acc[ii][jj];
            d2 = fmaxf(d2, 0.f);
            dst[ii][jj] = sqrtf(d2 + 1e-12f);
        }
    }

    const float iv[NKER] = { 1.f / (bw[0] * bw[0]), 1.f / bw[1],
                             1.f / (bw[2] * bw[2]), 1.f / bw[3] };
    float dsum[NKER] = {0.f, 0.f, 0.f, 0.f};

    const int w = tid >> 5, lane = tid & 31;

    #pragma unroll
    for (int k = 0; k < NKER; k++) {
        uint32_t pkU[2][4], pkD[2][4];
        #pragma unroll
        for (int ii = 0; ii < 2; ii++) {
            const int gi = i0 + ty * 2 + ii;
            #pragma unroll
            for (int jj = 0; jj < 4; jj++) {
                const int gj = j0 + tx * 4 + jj;
                float dist = dst[ii][jj];
                float arg = (k & 1) ? (-dist * iv[k]) : (-dist * dist * iv[k]);
                float kv = __expf(arg);
                bool zr = (gi < NHALF) && (gj == gi + NHALF);
                if (zr) g_z[k][gi] = kv;
                if (gi == gj) dsum[k] += kv;
                __nv_bfloat16 h = __float2bfloat16(kv);
                __nv_bfloat16 m = __float2bfloat16(kv - __bfloat162float(h));
                __nv_bfloat162 pr(h, m);
                uint32_t u = *(uint32_t*)&pr;
                pkU[ii][jj] = u;
                pkD[ii][jj] = zr ? 0u : u;
            }
        }
        // direct writes (zeroed where required)
        #pragma unroll
        for (int ii = 0; ii < 2; ii++) {
            const size_t base = (size_t)(i0 + ty * 2 + ii) * NPTS + j0 + tx * 4;
            uint2 hv, mv;
            hv.x = __byte_perm(pkD[ii][0], pkD[ii][1], 0x5410);
            hv.y = __byte_perm(pkD[ii][2], pkD[ii][3], 0x5410);
            mv.x = __byte_perm(pkD[ii][0], pkD[ii][1], 0x7632);
            mv.y = __byte_perm(pkD[ii][2], pkD[ii][3], 0x7632);
            *(uint2*)&g_Khi[k][base] = hv;
            *(uint2*)&g_Kmd[k][base] = mv;
            *(uint4*)&g_Kpk[k][base] = make_uint4(pkD[ii][0], pkD[ii][1],
                                                  pkD[ii][2], pkD[ii][3]);
        }
        // mirrored tile (un-zeroed) via smem transpose
        if (!diag) {
            __syncthreads();
            #pragma unroll
            for (int ii = 0; ii < 2; ii++) {
                #pragma unroll
                for (int jj = 0; jj < 4; jj++)
                    smT[ty * 2 + ii][tx * 4 + jj] = pkU[ii][jj];
            }
            __syncthreads();
            const int rr = tid >> 2;             // 0..31 transposed row (orig col)
            const int cc0 = (tid & 3) * 8;       // 8 consecutive orig rows
            uint32_t v[8];
            #pragma unroll
            for (int q = 0; q < 8; q++) v[q] = smT[rr][cc0 + q];   // wait: see below
            // NOTE: smT[r][c] holds value at (orig row r, orig col c).
            // transposed element (row=j0+rr? ) -- we need column rr of original:
            // v[q] must be smT[cc0+q][rr]
            #pragma unroll
            for (int q = 0; q < 8; q++) v[q] = smT[cc0 + q][rr];
            const size_t base = (size_t)(j0 + rr) * NPTS + i0 + cc0;
            uint2 hv0, hv1, mv0, mv1;
            hv0.x = __byte_perm(v[0], v[1], 0x5410);
            hv0.y = __byte_perm(v[2], v[3], 0x5410);
            hv1.x = __byte_perm(v[4], v[5], 0x5410);
            hv1.y = __byte_perm(v[6], v[7], 0x5410);
            mv0.x = __byte_perm(v[0], v[1], 0x7632);
            mv0.y = __byte_perm(v[2], v[3], 0x7632);
            mv1.x = __byte_perm(v[4], v[5], 0x7632);
            mv1.y = __byte_perm(v[6], v[7], 0x7632);
            *(uint2*)&g_Khi[k][base]     = hv0;
            *(uint2*)&g_Khi[k][base + 4] = hv1;
            *(uint2*)&g_Kmd[k][base]     = mv0;
            *(uint2*)&g_Kmd[k][base + 4] = mv1;
            *(uint4*)&g_Kpk[k][base]     = make_uint4(v[0], v[1], v[2], v[3]);
            *(uint4*)&g_Kpk[k][base + 4] = make_uint4(v[4], v[5], v[6], v[7]);
        }
    }

    // diag blocks: deterministic reduce of diagonal sums
    if (diag) {
        #pragma unroll
        for (int k = 0; k < NKER; k++) {
            float v = warpred(dsum[k]);
            if (lane == 0) dsh[w][k] = v;
        }
        __syncthreads();
        if (tid == 0) {
            #pragma unroll
            for (int k = 0; k < NKER; k++)
                g_DtP[k][bi] = dsh[0][k] + dsh[1][k] + dsh[2][k] + dsh[3][k];
        }
    }
}

// ---------------- kernel 2: mma.sync signed GEMM -> T partials -----------
// grid (6 n-tiles, 4 p-tiles, kk*2+ksplit); 256 threads (8 warps: 4m x 2n).
__global__ void __launch_bounds__(256) k_mma() {
    __shared__ __align__(16) unsigned char As[2][64 * 128];    // 16 KB
    __shared__ __align__(16) unsigned char Bs[2][128 * 128];   // 32 KB
    const int nt = blockIdx.x, pt = blockIdx.y;
    const int kk = blockIdx.z >> 1, ks = blockIdx.z & 1;
    const int tid = threadIdx.x, w = tid >> 5, lane = tid & 31;
    const int wm = w & 3, wn = w >> 2;
    const uint32_t aBase = s2u(&As[0][0]);
    const uint32_t bBase = s2u(&Bs[0][0]);
    const __nv_bfloat16* __restrict__ KP = ks ? g_Kmd[kk] : g_Khi[kk];

    float d[8][4] = {};

    auto load = [&](int ch, int buf) {
        const int a0 = ch * 64;
        #pragma unroll 2
        for (int idx = tid; idx < 512; idx += 256) {        // A: 64 rows x 128B
            int r = idx >> 3, c = idx & 7;
            uint4 v = *(const uint4*)&g_mbf[pt * 64 + r][a0 + c * 8];
            *(uint4*)&As[buf][r * 128 + ((c ^ (r & 7)) << 4)] = v;
        }
        #pragma unroll 4
        for (int idx = tid; idx < 1024; idx += 256) {       // B: 128 rows x 128B
            int r = idx >> 3, c = idx & 7;
            uint4 v = *(const uint4*)&KP[(size_t)(nt * 128 + r) * NPTS + a0 + c * 8];
            *(uint4*)&Bs[buf][r * 128 + ((c ^ (r & 7)) << 4)] = v;
        }
    };

    load(0, 0);
    __syncthreads();
    for (int ch = 0; ch < 12; ch++) {
        const int buf = ch & 1;
        if (ch + 1 < 12) load(ch + 1, buf ^ 1);
        #pragma unroll
        for (int ksq = 0; ksq < 4; ksq++) {
            uint32_t a[4];
            {
                int r = wm * 16 + (lane & 15);
                int c = ksq * 2 + (lane >> 4);
                uint32_t addr = aBase + buf * 8192 + r * 128 + ((c ^ (r & 7)) << 4);
                asm volatile("ldmatrix.sync.aligned.m8n8.x4.shared.b16 {%0,%1,%2,%3}, [%4];"
                             : "=r"(a[0]), "=r"(a[1]), "=r"(a[2]), "=r"(a[3]) : "r"(addr));
            }
            #pragma unroll
            for (int j = 0; j < 8; j++) {
                uint32_t b[2];
                int r = wn * 64 + j * 8 + (lane & 7);
                int c = ksq * 2 + ((lane >> 3) & 1);
                uint32_t addr = bBase + buf * 16384 + r * 128 + ((c ^ (r & 7)) << 4);
                asm volatile("ldmatrix.sync.aligned.m8n8.x2.shared.b16 {%0,%1}, [%2];"
                             : "=r"(b[0]), "=r"(b[1]) : "r"(addr));
                asm volatile("mma.sync.aligned.m16n8k16.row.col.f32.bf16.bf16.f32 "
                             "{%0,%1,%2,%3}, {%4,%5,%6,%7}, {%8,%9}, {%0,%1,%2,%3};"
                             : "+f"(d[j][0]), "+f"(d[j][1]), "+f"(d[j][2]), "+f"(d[j][3])
                             : "r"(a[0]), "r"(a[1]), "r"(a[2]), "r"(a[3]),
                               "r"(b[0]), "r"(b[1]));
            }
        }
        __syncthreads();
    }

    // epilogue: partial T[p] = sum_b s[p][b] * D'[p][b]
    const int lq = lane >> 2, lr = lane & 3;
    const int p0 = pt * 64 + wm * 16 + lq;
    const int p1 = p0 + 8;
    float part0 = 0.f, part1 = 0.f;
    #pragma unroll
    for (int j = 0; j < 8; j++) {
        int b0 = nt * 128 + wn * 64 + j * 8 + lr * 2;
        float m0 = __bfloat162float(g_mbf[p0][b0]);
        float m1 = __bfloat162float(g_mbf[p0][b0 + 1]);
        part0 += d[j][0] * m0 + d[j][1] * m1;
        float n0 = __bfloat162float(g_mbf[p1][b0]);
        float n1 = __bfloat162float(g_mbf[p1][b0 + 1]);
        part1 += d[j][2] * n0 + d[j][3] * n1;
    }
    part0 += __shfl_xor_sync(0xffffffffu, part0, 1);
    part0 += __shfl_xor_sync(0xffffffffu, part0, 2);
    part1 += __shfl_xor_sync(0xffffffffu, part1, 1);
    part1 += __shfl_xor_sync(0xffffffffu, part1, 2);
    if (lr == 0) {
        const int sub = ks * 12 + nt * 2 + wn;
        g_part[kk][sub][p0] = part0;
        g_part[kk][sub][p1] = part1;
    }
}

// ---------------- kernel 3: phase 2 per-(slot, kernel) combine -----------
// Ub = (C1/4)*T + sum_{a in A} (+-z[a])/nm + C4*cross + (S*CS - Dt/nn)
__global__ void __launch_bounds__(128) k_phase2(const int* __restrict__ perms,
                                                float* __restrict__ out) {
    const int p = blockIdx.x;          // 0..200
    const int kk = blockIdx.y;
    const int tid = threadIdx.x;       // 128
    __shared__ float sm[3][4];
    const bool ident = (p == NPER);

    const uint32_t* __restrict__ Kp = g_Kpk[kk];
    const float* __restrict__ Zc = g_z[kk];

    float t1 = 0.f, cr = 0.f, aux = 0.f;
    #pragma unroll
    for (int it = 0; it < 3; it++) {
        int j = tid + it * 128;
        int a = ident ? j : __ldg(&perms[p * NPTS + j]);
        int b = ident ? (NHALF + j) : __ldg(&perms[p * NPTS + NHALF + j]);
        t1 += (a < NHALF) ? (INV_NM * Zc[a]) : (-INV_NM * Zc[a - NHALF]);
        uint32_t wv = __ldg(&Kp[a * NPTS + b]);
        __nv_bfloat162 v = *reinterpret_cast<__nv_bfloat162*>(&wv);
        cr += __bfloat162float(v.x) + __bfloat162float(v.y);
    }
    if (tid < 24) {
        t1 += C14 * g_part[kk][tid][p];
        aux += CS * g_part[kk][tid][201];          // S*CS partials
    }
    if (tid >= 32 && tid < 56)
        aux -= INV_NN * g_DtP[kk][tid - 32];       // -Dt/nn partials

    float r1 = warpred(t1), r2 = warpred(cr), r3 = warpred(aux);
    if ((tid & 31) == 0) {
        sm[0][tid >> 5] = r1; sm[1][tid >> 5] = r2; sm[2][tid >> 5] = r3;
    }
    __syncthreads();
    if (tid == 0) {
        float T1 = sm[0][0] + sm[0][1] + sm[0][2] + sm[0][3];
        float CR = sm[1][0] + sm[1][1] + sm[1][2] + sm[1][3];
        float AX = sm[2][0] + sm[2][1] + sm[2][2] + sm[2][3];
        float Ub = T1 + C4 * CR + AX;
        int idx = ident ? (kk * (NPER + 1)) : (kk * (NPER + 1) + 1 + p);
        out[idx] = Ub;
    }
}

// ---------------- launch ----------------
extern "C" void kernel_launch(void* const* d_in, const int* in_sizes, int n_in,
                              void* d_out, int out_size) {
    const float* X     = (const float*)d_in[0];
    const float* Y     = (const float*)d_in[1];
    const float* bw    = (const float*)d_in[2];
    const int*   perms = (const int*)d_in[3];
    float* out = (float*)d_out;

    k_pairmask<<<NSLOT + NTRI, 128>>>(X, Y, bw, perms);
    k_mma<<<dim3(6, 4, 8), 256>>>();
    k_phase2<<<dim3(NPER + 1, NKER), 128>>>(perms, out);
}